// round 17
// baseline (speedup 1.0000x reference)
#include <cuda_runtime.h>
#include <math.h>

#define DD 96
#define NPART 48
#define PITCH 97
#define NTHREADS 512

__device__ float g_G[DD * DD];
__device__ double g_pk[NPART];
__device__ unsigned int g_count = 0;

// fp32 reciprocal: rcp.approx seed + 1 Newton step (~2^-22 rel).
__device__ __forceinline__ float fast_recip_f(float p) {
    float r;
    asm("rcp.approx.f32 %0, %1;" : "=f"(r) : "f"(p));
    r = r * __fmaf_rn(-p, r, 2.0f);
    return r;
}

// ---------------------------------------------------------------------------
// G = I - P P^T in fp32 (96 blocks x 96 threads; measured-best shape).
// ---------------------------------------------------------------------------
__global__ void build_G_kernel(const float* __restrict__ P) {
    __shared__ float Pt[NPART][DD];  // Pt[t][i] = P[i*NPART+t]
    const int i = blockIdx.x;
    const int tid = threadIdx.x;  // 96

    for (int idx = tid; idx < DD * NPART; idx += DD) {
        int r = idx / NPART;
        int t = idx - r * NPART;
        Pt[t][r] = P[idx];
    }
    __syncthreads();

    const int j = tid;
    float a0 = 0.f, a1 = 0.f, a2 = 0.f, a3 = 0.f;
#pragma unroll
    for (int t = 0; t < NPART; t += 4) {
        a0 = __fmaf_rn(Pt[t][i],     Pt[t][j],     a0);
        a1 = __fmaf_rn(Pt[t + 1][i], Pt[t + 1][j], a1);
        a2 = __fmaf_rn(Pt[t + 2][i], Pt[t + 2][j], a2);
        a3 = __fmaf_rn(Pt[t + 3][i], Pt[t + 3][j], a3);
    }
    g_G[i * DD + j] = ((i == j) ? 1.0f : 0.0f) - ((a0 + a1) + (a2 + a3));
}

// ---------------------------------------------------------------------------
// fp32 rank-2 symmetric elimination, ONE barrier per two pivots.
// Warp 0 preps the next pivot pair with ALL coefficients (la,lb,lc,ld,f2,
// p2,p3,inv2,inv3) computed REDUNDANTLY per-lane from broadcast LDS scalars
// -> no shfl, no __syncwarp, and the two pivot-row vector loops fuse into one
// pipelined loop (v3 uses v2 from the same lane's register).
// Warps 1..15: rank-2 trailing update.  Prefix product + sample in fp64.
// ---------------------------------------------------------------------------
__global__ void __launch_bounds__(NTHREADS, 1)
lu_probs_kernel(const int* __restrict__ occ, float* __restrict__ out) {
    extern __shared__ float A_[];      // [DD][PITCH] dynamic, fp32
    __shared__ float U[2][2][DD];      // pair-buffered pivot rows
    __shared__ float s_inv[2][2];
    __shared__ float s_piv[DD];
    __shared__ double sc[2][DD];
    __shared__ int s_occ[NPART];
    __shared__ int s_last;

    const int k = blockIdx.x;
    const int m = DD - NPART + k + 1;   // 49 + k
    const int tid = threadIdx.x;        // 512
    const int tx = tid & 31;
    const int ty = tid >> 5;            // 0..15

    if (tid < NPART) s_occ[tid] = occ[tid];

    // Load leading m x m block of G.
    for (int r = ty; r < m; r += 16)
        for (int c = tx; c < m; c += 32)
            A_[r * PITCH + c] = g_G[r * DD + c];
    __syncthreads();
    if (tid < k) {                      // distinct positions -> race-free
        int p = s_occ[tid];
        if (p < m) A_[p * PITCH + p] -= 1.0f;
    }
    __syncthreads();

    // Init: pivot rows 0 and 1 (scalar-coefficient form, warp 0).
    if (tid < m) U[0][0][tid] = A_[tid];
    if (tid == 0) {
        float p0 = A_[0];
        s_piv[0] = p0;
        s_inv[0][0] = fast_recip_f(p0);
    }
    __syncthreads();
    if (ty == 0) {
        const float inv0 = s_inv[0][0];
        const float* __restrict__ u0 = U[0][0];
        const float l1 = u0[1] * inv0;
        const float p1 = __fmaf_rn(-l1, u0[1], A_[PITCH + 1]);
        for (int c = 1 + tx; c < m; c += 32)
            U[0][1][c] = __fmaf_rn(-l1, u0[c], A_[PITCH + c]);
        if (tx == 0) {
            s_piv[1] = p1;
            s_inv[0][1] = fast_recip_f(p1);
        }
    }
    __syncthreads();

    for (int i0 = 0; i0 + 2 < m; i0 += 2) {
        const int pb = (i0 >> 1) & 1;
        const float inv0 = s_inv[pb][0];
        const float inv1 = s_inv[pb][1];
        const float* __restrict__ u0 = U[pb][0];
        const float* __restrict__ u1 = U[pb][1];
        const int r2 = i0 + 2, r3 = i0 + 3;

        if (ty == 0) {
            float* __restrict__ v2 = U[pb ^ 1][0];
            float* __restrict__ v3 = U[pb ^ 1][1];
            const float* __restrict__ arow2 = &A_[r2 * PITCH];

            // ---- redundant scalar chain (broadcast LDS, no shfl) ----
            const float u0r2 = u0[r2], u1r2 = u1[r2];
            const float la = u0r2 * inv0, lb = u1r2 * inv1;
            float p2 = arow2[r2];
            p2 = __fmaf_rn(-la, u0r2, p2);
            p2 = __fmaf_rn(-lb, u1r2, p2);
            const float inv2 = fast_recip_f(p2);

            if (r3 < m) {
                const float* __restrict__ arow3 = &A_[r3 * PITCH];
                const float u0r3 = u0[r3], u1r3 = u1[r3];
                const float lc = u0r3 * inv0, ld = u1r3 * inv1;
                float v2r3 = arow2[r3];
                v2r3 = __fmaf_rn(-la, u0r3, v2r3);
                v2r3 = __fmaf_rn(-lb, u1r3, v2r3);
                const float f2 = v2r3 * inv2;
                float p3 = arow3[r3];
                p3 = __fmaf_rn(-lc, u0r3, p3);
                p3 = __fmaf_rn(-ld, u1r3, p3);
                p3 = __fmaf_rn(-f2, v2r3, p3);
                if (tx == 0) {
                    s_piv[r2] = p2;
                    s_piv[r3] = p3;
                    s_inv[pb ^ 1][0] = inv2;
                    s_inv[pb ^ 1][1] = fast_recip_f(p3);
                }
                // ---- fused vector loop: v2 and v3 together, pipelined ----
                for (int c = r2 + tx; c < m; c += 32) {
                    const float u0c = u0[c], u1c = u1[c];
                    float a2 = arow2[c];
                    a2 = __fmaf_rn(-la, u0c, a2);
                    a2 = __fmaf_rn(-lb, u1c, a2);
                    v2[c] = a2;
                    float a3 = arow3[c];
                    a3 = __fmaf_rn(-lc, u0c, a3);
                    a3 = __fmaf_rn(-ld, u1c, a3);
                    a3 = __fmaf_rn(-f2, a2, a3);
                    v3[c] = a3;
                }
            } else {
                if (tx == 0) {
                    s_piv[r2] = p2;
                    s_inv[pb ^ 1][0] = inv2;
                }
                for (int c = r2 + tx; c < m; c += 32) {
                    float a2 = arow2[c];
                    a2 = __fmaf_rn(-la, u0[c], a2);
                    a2 = __fmaf_rn(-lb, u1[c], a2);
                    v2[c] = a2;
                }
            }
        } else {
            // Rank-2 trailing update of rows i0+4 .. m-1 (stride 15).
            for (int r = i0 + 3 + ty; r < m; r += 15) {
                const float la = u0[r] * inv0;
                const float lb = u1[r] * inv1;
                float* __restrict__ arow = &A_[r * PITCH];
                for (int c = r2 + tx; c < m; c += 32) {
                    float v = arow[c];
                    v = __fmaf_rn(-la, u0[c], v);
                    v = __fmaf_rn(-lb, u1[c], v);
                    arow[c] = v;
                }
            }
        }
        __syncthreads();
    }

    const int xmin = (k == 0) ? 0 : s_occ[k - 1] + 1;

    // Inclusive prefix product of pivots masked to [xmin, m) — in fp64.
    if (tid < DD)
        sc[0][tid] = (tid >= xmin && tid < m) ? (double)s_piv[tid] : 1.0;
    __syncthreads();
    int src = 0;
    for (int off = 1; off < DD; off <<= 1) {
        if (tid < DD) {
            double v = sc[src][tid];
            if (tid >= off) v *= sc[src][tid - off];
            sc[src ^ 1][tid] = v;
        }
        __syncthreads();
        src ^= 1;
    }

    if (tid < DD) {
        const int x = tid;
        double pr = 0.0;
        if (x >= xmin && x < m) {
            const double S = (x == xmin) ? 1.0 : sc[src][x - 1];
            pr = -S * ((double)s_piv[x] - 1.0);
            if (!(fabs(pr) > 1e-15)) pr = 0.0;
        }
        out[k * DD + x] = (float)pr;
        if (x == s_occ[k]) g_pk[k] = pr;
    }

    // ---- fused prob_sample: last block to finish multiplies g_pk ----
    __syncthreads();
    if (tid == 0) {
        __threadfence();
        unsigned int n = atomicAdd(&g_count, 1u);
        s_last = (n == NPART - 1) ? 1 : 0;
    }
    __syncthreads();
    if (s_last) {
        if (tid < 32) {
            volatile double* vp = g_pk;
            double v = vp[tid];
            if (tid < 16) v *= vp[32 + tid];
#pragma unroll
            for (int off = 16; off > 0; off >>= 1)
                v *= __shfl_xor_sync(0xFFFFFFFFu, v, off);
            if (tid == 0) {
                out[NPART * DD] = (float)v;
                g_count = 0;  // reset for next graph replay
            }
        }
    }
}

extern "C" void kernel_launch(void* const* d_in, const int* in_sizes, int n_in,
                              void* d_out, int out_size) {
    const float* P;
    const int* occ;
    if (in_sizes[0] == DD * NPART) {
        P = (const float*)d_in[0];
        occ = (const int*)d_in[1];
    } else {
        P = (const float*)d_in[1];
        occ = (const int*)d_in[0];
    }
    float* out = (float*)d_out;

    const int smem = DD * PITCH * (int)sizeof(float);  // 37248 B
    cudaFuncSetAttribute(lu_probs_kernel,
                         cudaFuncAttributeMaxDynamicSharedMemorySize, smem);

    build_G_kernel<<<DD, DD>>>(P);
    lu_probs_kernel<<<NPART, NTHREADS, smem>>>(occ, out);
}